// round 2
// baseline (speedup 1.0000x reference)
#include <cuda_runtime.h>

#define NN 100000
#define NE 3200000
#define ET (NE + NN)

// ---------------- scratch (device globals; no allocs allowed) ----------------
__device__ __align__(128) int   g_cnt[NN];        // counts, then scatter cursor
__device__ __align__(128) int   g_off[NN + 1];    // CSR offsets by dst
__device__ __align__(128) int   g_csr[ET];        // src node id per CSR slot
__device__ __align__(128) float g_h[NN * 32];     // node features in  (stride = CH of layer)
__device__ __align__(128) float g_o[NN * 32];     // aggregated out
__device__ __align__(128) float g_als[NN * 2];    // per-node src-attention scalar [n][h]
__device__ __align__(128) float g_ald[NN * 2];    // per-node dst-attention scalar [n][h]

// ---------------- CSR build ----------------
__global__ void k_zero() {
    int i = blockIdx.x * blockDim.x + threadIdx.x;
    if (i < NN) g_cnt[i] = 0;
}

__global__ void k_count(const int* __restrict__ dst) {
    int e = blockIdx.x * blockDim.x + threadIdx.x;
    if (e >= ET) return;
    int d = (e < NE) ? dst[e] : (e - NE);   // append self-loops
    atomicAdd(&g_cnt[d], 1);
}

// single-block exclusive scan of g_cnt -> g_off; g_cnt becomes the cursor copy
__global__ void k_scan() {
    __shared__ int sm[1024];
    const int T = 1024;
    int tid = threadIdx.x;
    const int chunk = (NN + T - 1) / T;   // 98
    int b = tid * chunk;
    int e = min(b + chunk, NN);
    int s = 0;
    for (int i = b; i < e; i++) s += g_cnt[i];
    sm[tid] = s;
    __syncthreads();
    // Hillis-Steele inclusive scan
    for (int d = 1; d < T; d <<= 1) {
        int t = (tid >= d) ? sm[tid - d] : 0;
        __syncthreads();
        if (tid >= d) sm[tid] += t;
        __syncthreads();
    }
    int run = sm[tid] - s;   // exclusive prefix for this thread's chunk
    for (int i = b; i < e; i++) {
        int c = g_cnt[i];
        g_off[i] = run;
        g_cnt[i] = run;      // cursor for scatter
        run += c;
    }
    if (tid == T - 1) g_off[NN] = sm[T - 1];
}

__global__ void k_scatter(const int* __restrict__ src, const int* __restrict__ dst) {
    int e = blockIdx.x * blockDim.x + threadIdx.x;
    if (e >= ET) return;
    int s, d;
    if (e < NE) { s = src[e]; d = dst[e]; } else { s = d = e - NE; }
    int pos = atomicAdd(&g_cnt[d], 1);
    g_csr[pos] = s;
}

// ---------------- layer 1 node transform: h = x @ W1, attention scalars ----------------
__global__ void k_node1(const float* __restrict__ x, const float* __restrict__ W,
                        const float* __restrict__ as_, const float* __restrict__ ad_) {
    int n = blockIdx.x * blockDim.x + threadIdx.x;
    if (n >= NN) return;
    float x0 = x[n * 3 + 0], x1 = x[n * 3 + 1], x2 = x[n * 3 + 2];
    float als0 = 0.f, als1 = 0.f, ald0 = 0.f, ald1 = 0.f;
#pragma unroll
    for (int c = 0; c < 32; c++) {
        float h = fmaf(x0, __ldg(&W[c]), fmaf(x1, __ldg(&W[32 + c]), x2 * __ldg(&W[64 + c])));
        g_h[n * 32 + c] = h;
        float vs = h * __ldg(&as_[c]), vd = h * __ldg(&ad_[c]);
        if (c < 16) { als0 += vs; ald0 += vd; }
        else        { als1 += vs; ald1 += vd; }
    }
    g_als[n * 2 + 0] = als0; g_als[n * 2 + 1] = als1;
    g_ald[n * 2 + 0] = ald0; g_ald[n * 2 + 1] = ald1;
}

// ---------------- edge aggregation: one warp per destination node ----------------
// reads g_h (stride CH), g_als/g_ald (stride H), writes g_o (stride CH)
template <int H, int CH>
__global__ void __launch_bounds__(128) k_edge() {
    int w = (blockIdx.x * blockDim.x + threadIdx.x) >> 5;
    int lane = threadIdx.x & 31;
    if (w >= NN) return;
    int start = g_off[w], end = g_off[w + 1];

    float aldv[H];
#pragma unroll
    for (int h = 0; h < H; h++) aldv[h] = g_ald[w * H + h];

    // pass 1: online softmax (running max + rescaled sum), lanes parallel over edges
    float m[H], ss[H];
#pragma unroll
    for (int h = 0; h < H; h++) { m[h] = -1e30f; ss[h] = 0.f; }
    for (int j = start + lane; j < end; j += 32) {
        int s = g_csr[j];
#pragma unroll
        for (int h = 0; h < H; h++) {
            float v = g_als[s * H + h] + aldv[h];
            v = v > 0.f ? v : 0.2f * v;              // leaky_relu(0.2)
            float mn = fmaxf(m[h], v);
            ss[h] = ss[h] * __expf(m[h] - mn) + __expf(v - mn);
            m[h] = mn;
        }
    }
    // warp combine
#pragma unroll
    for (int o = 16; o > 0; o >>= 1) {
#pragma unroll
        for (int h = 0; h < H; h++) {
            float mo = __shfl_xor_sync(0xffffffffu, m[h], o);
            float so = __shfl_xor_sync(0xffffffffu, ss[h], o);
            float mn = fmaxf(m[h], mo);
            ss[h] = ss[h] * __expf(m[h] - mn) + so * __expf(mo - mn);
            m[h] = mn;
        }
    }
    float inv[H];
#pragma unroll
    for (int h = 0; h < H; h++) inv[h] = 1.f / (ss[h] + 1e-16f);

    // pass 2: weighted gather-sum; lane = output channel, serial over edges in chunks
    float acc = 0.f;
    for (int base = start; base < end; base += 32) {
        int j = base + lane;
        int s = 0;
        float a[H];
#pragma unroll
        for (int h = 0; h < H; h++) a[h] = 0.f;
        if (j < end) {
            s = g_csr[j];
#pragma unroll
            for (int h = 0; h < H; h++) {
                float v = g_als[s * H + h] + aldv[h];
                v = v > 0.f ? v : 0.2f * v;
                a[h] = __expf(v - m[h]) * inv[h];
            }
        }
        int cnt = min(32, end - base);
        for (int k = 0; k < cnt; k++) {
            int sk = __shfl_sync(0xffffffffu, s, k);
            float wgt;
            if (H == 2) {
                float w0 = __shfl_sync(0xffffffffu, a[0], k);
                float w1 = __shfl_sync(0xffffffffu, a[1], k);
                wgt = (lane < (CH / H)) ? w0 : w1;
            } else {
                wgt = __shfl_sync(0xffffffffu, a[0], k);
            }
            if (lane < CH) acc = fmaf(wgt, g_h[sk * CH + lane], acc);  // coalesced 128B line
        }
    }
    if (lane < CH) g_o[w * CH + lane] = acc;
}

// ---------------- mid node transform: z = elu(prev + b); h = z @ W; attention scalars ----
// reads g_o (stride CIN), writes g_h (stride COUT), g_als/g_ald (stride H)
template <int CIN, int COUT, int H>
__global__ void k_mid(const float* __restrict__ b, const float* __restrict__ W,
                      const float* __restrict__ as_, const float* __restrict__ ad_) {
    __shared__ float sW[CIN * COUT];
    __shared__ float sb[CIN];
    __shared__ float sas[COUT], sad[COUT];
    for (int i = threadIdx.x; i < CIN * COUT; i += blockDim.x) sW[i] = W[i];
    for (int i = threadIdx.x; i < CIN; i += blockDim.x) sb[i] = b[i];
    for (int i = threadIdx.x; i < COUT; i += blockDim.x) { sas[i] = as_[i]; sad[i] = ad_[i]; }
    __syncthreads();

    int n = blockIdx.x * blockDim.x + threadIdx.x;
    if (n >= NN) return;
    float z[CIN];
#pragma unroll
    for (int i = 0; i < CIN; i++) {
        float v = g_o[n * CIN + i] + sb[i];
        z[i] = v > 0.f ? v : expm1f(v);              // elu
    }
    const int C = COUT / H;
    float als[H], ald[H];
#pragma unroll
    for (int h = 0; h < H; h++) { als[h] = 0.f; ald[h] = 0.f; }
#pragma unroll
    for (int c = 0; c < COUT; c++) {
        float hv = 0.f;
#pragma unroll
        for (int i = 0; i < CIN; i++) hv = fmaf(z[i], sW[i * COUT + c], hv);
        g_h[n * COUT + c] = hv;
        int h = c / C;
        als[h] = fmaf(hv, sas[c], als[h]);
        ald[h] = fmaf(hv, sad[c], ald[h]);
    }
#pragma unroll
    for (int h = 0; h < H; h++) { g_als[n * H + h] = als[h]; g_ald[n * H + h] = ald[h]; }
}

// ---------------- final: y = elu(out3 + b3) @ Wo + bo ----------------
__global__ void k_final(const float* __restrict__ b3, const float* __restrict__ Wo,
                        const float* __restrict__ bo, float* __restrict__ out) {
    int n = blockIdx.x * blockDim.x + threadIdx.x;
    if (n >= NN) return;
    float acc = bo[0];
#pragma unroll
    for (int c = 0; c < 8; c++) {
        float v = g_o[n * 8 + c] + b3[c];
        v = v > 0.f ? v : expm1f(v);
        acc = fmaf(v, Wo[c], acc);
    }
    out[n] = acc;
}

// ---------------- launch ----------------
extern "C" void kernel_launch(void* const* d_in, const int* in_sizes, int n_in,
                              void* d_out, int out_size) {
    const float* x   = (const float*)d_in[0];
    const int*   ei  = (const int*)d_in[1];
    const float* W1  = (const float*)d_in[2];
    const float* as1 = (const float*)d_in[3];
    const float* ad1 = (const float*)d_in[4];
    const float* b1  = (const float*)d_in[5];
    const float* W2  = (const float*)d_in[6];
    const float* as2 = (const float*)d_in[7];
    const float* ad2 = (const float*)d_in[8];
    const float* b2  = (const float*)d_in[9];
    const float* W3  = (const float*)d_in[10];
    const float* as3 = (const float*)d_in[11];
    const float* ad3 = (const float*)d_in[12];
    const float* b3  = (const float*)d_in[13];
    const float* Wo  = (const float*)d_in[14];
    const float* bo  = (const float*)d_in[15];
    float* out = (float*)d_out;

    const int* src = ei;
    const int* dst = ei + NE;

    // CSR build (topology identical every call; build is part of the deterministic work)
    k_zero<<<(NN + 255) / 256, 256>>>();
    k_count<<<(ET + 255) / 256, 256>>>(dst);
    k_scan<<<1, 1024>>>();
    k_scatter<<<(ET + 255) / 256, 256>>>(src, dst);

    const int EDGE_BLOCKS = (NN * 32 + 127) / 128;   // 1 warp per dst node, 4 warps/CTA
    // layer 1 (H=2, C=16)
    k_node1<<<(NN + 255) / 256, 256>>>(x, W1, as1, ad1);
    k_edge<2, 32><<<EDGE_BLOCKS, 128>>>();
    // layer 2 (H=2, C=16)
    k_mid<32, 32, 2><<<(NN + 255) / 256, 256>>>(b1, W2, as2, ad2);
    k_edge<2, 32><<<EDGE_BLOCKS, 128>>>();
    // layer 3 (H=1, C=8)
    k_mid<32, 8, 1><<<(NN + 255) / 256, 256>>>(b2, W3, as3, ad3);
    k_edge<1, 8><<<EDGE_BLOCKS, 128>>>();
    // output head
    k_final<<<(NN + 255) / 256, 256>>>(b3, Wo, bo, out);

    (void)in_sizes; (void)n_in; (void)out_size;
}

// round 4
// speedup vs baseline: 1.1922x; 1.1922x over previous
#include <cuda_runtime.h>

#define NN 100000
#define NE 3200000
#define ET (NE + NN)
#define SMAX 128
#define NW 8   // warps per edge-kernel block

// ---------------- scratch (device globals; no allocs allowed) ----------------
__device__ __align__(128) int   g_cnt[NN];        // counts (init 1 for self-loop), then cursor
__device__ __align__(128) int   g_off[NN + 1];    // CSR offsets by dst
__device__ __align__(128) int   g_csr[ET];        // src node id per CSR slot
__device__ __align__(128) float g_h[NN * 32];     // node features (stride = CH of layer)
__device__ __align__(128) float g_o[NN * 32];     // aggregated out
__device__ __align__(128) float g_als[NN * 2];    // per-node src-attention scalar [n][h]
__device__ __align__(128) float g_ald[NN * 2];    // per-node dst-attention scalar [n][h]

// ---------------- CSR build ----------------
__global__ void k_zero() {
    int i = blockIdx.x * blockDim.x + threadIdx.x;
    if (i < NN) g_cnt[i] = 1;          // self-loop pre-counted
}

__global__ void k_count(const int4* __restrict__ dst4) {
    int e = blockIdx.x * blockDim.x + threadIdx.x;
    if (e >= NE / 4) return;
    int4 d = dst4[e];
    atomicAdd(&g_cnt[d.x], 1);
    atomicAdd(&g_cnt[d.y], 1);
    atomicAdd(&g_cnt[d.z], 1);
    atomicAdd(&g_cnt[d.w], 1);
}

// single-block exclusive scan; also places the self-loop and sets cursor past it
__global__ void k_scan() {
    __shared__ int sm[1024];
    const int T = 1024;
    int tid = threadIdx.x;
    const int chunk = (NN + T - 1) / T;   // 98
    int b = tid * chunk;
    int e = min(b + chunk, NN);
    int s = 0;
    for (int i = b; i < e; i++) s += g_cnt[i];
    sm[tid] = s;
    __syncthreads();
    for (int d = 1; d < T; d <<= 1) {
        int t = (tid >= d) ? sm[tid - d] : 0;
        __syncthreads();
        if (tid >= d) sm[tid] += t;
        __syncthreads();
    }
    int run = sm[tid] - s;   // exclusive prefix of this thread's chunk
    for (int i = b; i < e; i++) {
        int c = g_cnt[i];
        g_off[i] = run;
        g_csr[run] = i;      // self-loop first
        g_cnt[i] = run + 1;  // cursor after self-loop
        run += c;
    }
    if (tid == T - 1) g_off[NN] = sm[T - 1];
}

__global__ void k_scatter(const int4* __restrict__ src4, const int4* __restrict__ dst4) {
    int e = blockIdx.x * blockDim.x + threadIdx.x;
    if (e >= NE / 4) return;
    int4 s = src4[e];
    int4 d = dst4[e];
    g_csr[atomicAdd(&g_cnt[d.x], 1)] = s.x;
    g_csr[atomicAdd(&g_cnt[d.y], 1)] = s.y;
    g_csr[atomicAdd(&g_cnt[d.z], 1)] = s.z;
    g_csr[atomicAdd(&g_cnt[d.w], 1)] = s.w;
}

// ---------------- layer 1 node transform ----------------
__global__ void k_node1(const float* __restrict__ x, const float* __restrict__ W,
                        const float* __restrict__ as_, const float* __restrict__ ad_) {
    int n = blockIdx.x * blockDim.x + threadIdx.x;
    if (n >= NN) return;
    float x0 = x[n * 3 + 0], x1 = x[n * 3 + 1], x2 = x[n * 3 + 2];
    float als0 = 0.f, als1 = 0.f, ald0 = 0.f, ald1 = 0.f;
#pragma unroll
    for (int c = 0; c < 32; c++) {
        float h = fmaf(x0, __ldg(&W[c]), fmaf(x1, __ldg(&W[32 + c]), x2 * __ldg(&W[64 + c])));
        g_h[n * 32 + c] = h;
        float vs = h * __ldg(&as_[c]), vd = h * __ldg(&ad_[c]);
        if (c < 16) { als0 += vs; ald0 += vd; }
        else        { als1 += vs; ald1 += vd; }
    }
    g_als[n * 2 + 0] = als0; g_als[n * 2 + 1] = als1;
    g_ald[n * 2 + 0] = ald0; g_ald[n * 2 + 1] = ald1;
}

__device__ __forceinline__ float lrelu(float v) { return v > 0.f ? v : 0.2f * v; }

// ---------------- edge aggregation, H=2 CH=32: one warp per dst ----------------
__global__ void __launch_bounds__(256) k_edge2() {
    __shared__ int   s_s[NW][SMAX];
    __shared__ float s_a[NW][SMAX * 2];   // [jj][h] interleaved (float2 per edge)
    int widx = threadIdx.x >> 5;
    int lane = threadIdx.x & 31;
    int w = blockIdx.x * NW + widx;       // NN % NW == 0 -> always valid

    int start = g_off[w];
    int deg   = g_off[w + 1] - start;
    float2 aldv = ((const float2*)g_ald)[w];

    // phase A: exp(logit) per edge, denominator, cache (src, e0, e1)
    float ss0 = 0.f, ss1 = 0.f;
    for (int jj = lane; jj < deg; jj += 32) {
        int s = g_csr[start + jj];
        float2 av = ((const float2*)g_als)[s];
        float e0 = __expf(lrelu(av.x + aldv.x));
        float e1 = __expf(lrelu(av.y + aldv.y));
        ss0 += e0; ss1 += e1;
        if (jj < SMAX) {
            s_s[widx][jj] = s;
            ((float2*)s_a[widx])[jj] = make_float2(e0, e1);
        }
    }
#pragma unroll
    for (int o = 16; o > 0; o >>= 1) {
        ss0 += __shfl_xor_sync(0xffffffffu, ss0, o);
        ss1 += __shfl_xor_sync(0xffffffffu, ss1, o);
    }
    __syncwarp();
    int   hsel  = lane >> 4;
    float inv_l = 1.f / ((hsel ? ss1 : ss0) + 1e-16f);
    float aldh  = hsel ? aldv.y : aldv.x;

    // phase C: lane = channel; unrolled gather-accumulate from smem-cached edges
    float acc = 0.f;
    int lim = min(deg, SMAX);
    int jj = 0;
    for (; jj + 4 <= lim; jj += 4) {
        int s0 = s_s[widx][jj + 0], s1 = s_s[widx][jj + 1];
        int s2 = s_s[widx][jj + 2], s3 = s_s[widx][jj + 3];
        float a0 = s_a[widx][(jj + 0) * 2 + hsel];
        float a1 = s_a[widx][(jj + 1) * 2 + hsel];
        float a2 = s_a[widx][(jj + 2) * 2 + hsel];
        float a3 = s_a[widx][(jj + 3) * 2 + hsel];
        acc = fmaf(a0, g_h[s0 * 32 + lane], acc);
        acc = fmaf(a1, g_h[s1 * 32 + lane], acc);
        acc = fmaf(a2, g_h[s2 * 32 + lane], acc);
        acc = fmaf(a3, g_h[s3 * 32 + lane], acc);
    }
#pragma unroll 1
    for (; jj < lim; jj++)
        acc = fmaf(s_a[widx][jj * 2 + hsel], g_h[s_s[widx][jj] * 32 + lane], acc);
#pragma unroll 1
    for (; jj < deg; jj++) {          // overflow fallback (deg > SMAX; ~never)
        int s = g_csr[start + jj];
        float2 av = ((const float2*)g_als)[s];
        float v = (hsel ? av.y : av.x) + aldh;
        acc = fmaf(__expf(lrelu(v)), g_h[s * 32 + lane], acc);
    }
    g_o[w * 32 + lane] = acc * inv_l;
}

// ---------------- layer 3 edges (H=1, CH=8) fused with output head ----------------
__global__ void __launch_bounds__(256) k_edge1_final(
        const float* __restrict__ b3, const float* __restrict__ Wo,
        const float* __restrict__ bo, float* __restrict__ out) {
    __shared__ int   s_s[NW][SMAX];
    __shared__ float s_a[NW][SMAX];
    int widx = threadIdx.x >> 5;
    int lane = threadIdx.x & 31;
    int w = blockIdx.x * NW + widx;

    int start = g_off[w];
    int deg   = g_off[w + 1] - start;
    float aldv = g_ald[w];

    float ss = 0.f;
    for (int jj = lane; jj < deg; jj += 32) {
        int s = g_csr[start + jj];
        float e = __expf(lrelu(g_als[s] + aldv));
        ss += e;
        if (jj < SMAX) { s_s[widx][jj] = s; s_a[widx][jj] = e; }
    }
#pragma unroll
    for (int o = 16; o > 0; o >>= 1) ss += __shfl_xor_sync(0xffffffffu, ss, o);
    __syncwarp();
    float inv = 1.f / (ss + 1e-16f);

    // phase C: lane = (edge group, channel): 4 edges x 8 channels
    int grp = lane >> 3, c = lane & 7;
    float acc = 0.f;
    int lim = min(deg, SMAX);
    for (int jj = grp; jj < lim; jj += 4)
        acc = fmaf(s_a[widx][jj], g_h[s_s[widx][jj] * 8 + c], acc);
#pragma unroll 1
    for (int jj = lim + grp; jj < deg; jj += 4) {   // overflow fallback
        int s = g_csr[start + jj];
        acc = fmaf(__expf(lrelu(g_als[s] + aldv)), g_h[s * 8 + c], acc);
    }
    acc += __shfl_xor_sync(0xffffffffu, acc, 8);
    acc += __shfl_xor_sync(0xffffffffu, acc, 16);

    // fused head: y = elu(out3 + b3) @ Wo + bo
    float z = acc * inv + __ldg(&b3[c]);
    z = z > 0.f ? z : expm1f(z);
    float p = z * __ldg(&Wo[c]);
    p += __shfl_xor_sync(0xffffffffu, p, 1);
    p += __shfl_xor_sync(0xffffffffu, p, 2);
    p += __shfl_xor_sync(0xffffffffu, p, 4);
    if (lane == 0) out[w] = p + __ldg(&bo[0]);
}

// ---------------- mid node transform ----------------
template <int CIN, int COUT, int H>
__global__ void k_mid(const float* __restrict__ b, const float* __restrict__ W,
                      const float* __restrict__ as_, const float* __restrict__ ad_) {
    __shared__ float sW[CIN * COUT];
    __shared__ float sb[CIN];
    __shared__ float sas[COUT], sad[COUT];
    for (int i = threadIdx.x; i < CIN * COUT; i += blockDim.x) sW[i] = W[i];
    for (int i = threadIdx.x; i < CIN; i += blockDim.x) sb[i] = b[i];
    for (int i = threadIdx.x; i < COUT; i += blockDim.x) { sas[i] = as_[i]; sad[i] = ad_[i]; }
    __syncthreads();

    int n = blockIdx.x * blockDim.x + threadIdx.x;
    if (n >= NN) return;
    float z[CIN];
#pragma unroll
    for (int i = 0; i < CIN; i++) {
        float v = g_o[n * CIN + i] + sb[i];
        z[i] = v > 0.f ? v : expm1f(v);              // elu
    }
    const int C = COUT / H;
    float als[H], ald[H];
#pragma unroll
    for (int h = 0; h < H; h++) { als[h] = 0.f; ald[h] = 0.f; }
#pragma unroll
    for (int c = 0; c < COUT; c++) {
        float hv = 0.f;
#pragma unroll
        for (int i = 0; i < CIN; i++) hv = fmaf(z[i], sW[i * COUT + c], hv);
        g_h[n * COUT + c] = hv;
        int h = c / C;
        als[h] = fmaf(hv, sas[c], als[h]);
        ald[h] = fmaf(hv, sad[c], ald[h]);
    }
#pragma unroll
    for (int h = 0; h < H; h++) { g_als[n * H + h] = als[h]; g_ald[n * H + h] = ald[h]; }
}

// ---------------- launch ----------------
extern "C" void kernel_launch(void* const* d_in, const int* in_sizes, int n_in,
                              void* d_out, int out_size) {
    const float* x   = (const float*)d_in[0];
    const int*   ei  = (const int*)d_in[1];
    const float* W1  = (const float*)d_in[2];
    const float* as1 = (const float*)d_in[3];
    const float* ad1 = (const float*)d_in[4];
    const float* b1  = (const float*)d_in[5];
    const float* W2  = (const float*)d_in[6];
    const float* as2 = (const float*)d_in[7];
    const float* ad2 = (const float*)d_in[8];
    const float* b2  = (const float*)d_in[9];
    const float* W3  = (const float*)d_in[10];
    const float* as3 = (const float*)d_in[11];
    const float* ad3 = (const float*)d_in[12];
    const float* b3  = (const float*)d_in[13];
    const float* Wo  = (const float*)d_in[14];
    const float* bo  = (const float*)d_in[15];
    float* out = (float*)d_out;

    const int4* src4 = (const int4*)ei;            // edge_index[0]
    const int4* dst4 = (const int4*)(ei + NE);     // edge_index[1]

    // CSR build by dst (self-loops folded into scan)
    k_zero<<<(NN + 255) / 256, 256>>>();
    k_count<<<(NE / 4 + 255) / 256, 256>>>(dst4);
    k_scan<<<1, 1024>>>();
    k_scatter<<<(NE / 4 + 255) / 256, 256>>>(src4, dst4);

    const int EB = NN / NW;   // 12500 blocks, one warp per dst node
    // layer 1 (H=2, C=16)
    k_node1<<<(NN + 255) / 256, 256>>>(x, W1, as1, ad1);
    k_edge2<<<EB, 256>>>();
    // layer 2 (H=2, C=16)
    k_mid<32, 32, 2><<<(NN + 255) / 256, 256>>>(b1, W2, as2, ad2);
    k_edge2<<<EB, 256>>>();
    // layer 3 (H=1, C=8) + fused output head
    k_mid<32, 8, 1><<<(NN + 255) / 256, 256>>>(b2, W3, as3, ad3);
    k_edge1_final<<<EB, 256>>>(b3, Wo, bo, out);

    (void)in_sizes; (void)n_in; (void)out_size;
}

// round 5
// speedup vs baseline: 2.0100x; 1.6859x over previous
#include <cuda_runtime.h>

#define NN 100000
#define NE 3200000
#define ET (NE + NN)
#define SMAX 128
#define NW 8            // warps per edge-kernel block
#define SCAN_BLK 256
#define NB ((NN + SCAN_BLK - 1) / SCAN_BLK)   // 391

// ---------------- scratch (device globals; no allocs allowed) ----------------
__device__ __align__(128) int   g_cnt[NN];        // counts (init 1 for self-loop), then cursor
__device__ __align__(128) int   g_off[NN + 1];    // CSR offsets by dst
__device__ __align__(128) int   g_csr[ET];        // src node id per CSR slot
__device__ __align__(128) int   g_blk[NB];        // per-block count sums -> exclusive prefixes
__device__ __align__(128) float g_h[NN * 32];     // node features (stride = CH of layer)
__device__ __align__(128) float g_o[NN * 32];     // aggregated out
__device__ __align__(128) float g_als[NN * 2];    // per-node src-attention scalar [n][h]
__device__ __align__(128) float g_ald[NN * 2];    // per-node dst-attention scalar [n][h]

// ---------------- CSR build ----------------
__global__ void k_zero() {
    int i = blockIdx.x * blockDim.x + threadIdx.x;
    if (i < NN) g_cnt[i] = 1;          // self-loop pre-counted
}

__global__ void k_count(const int4* __restrict__ dst4) {
    int e = blockIdx.x * blockDim.x + threadIdx.x;
    if (e >= NE / 4) return;
    int4 d = dst4[e];
    atomicAdd(&g_cnt[d.x], 1);
    atomicAdd(&g_cnt[d.y], 1);
    atomicAdd(&g_cnt[d.z], 1);
    atomicAdd(&g_cnt[d.w], 1);
}

// per-block sums of g_cnt (391 blocks x 256 nodes)
__global__ void k_blksum() {
    __shared__ int sm[SCAN_BLK];
    int n = blockIdx.x * SCAN_BLK + threadIdx.x;
    sm[threadIdx.x] = (n < NN) ? g_cnt[n] : 0;
    __syncthreads();
#pragma unroll
    for (int o = SCAN_BLK / 2; o > 0; o >>= 1) {
        if (threadIdx.x < o) sm[threadIdx.x] += sm[threadIdx.x + o];
        __syncthreads();
    }
    if (threadIdx.x == 0) g_blk[blockIdx.x] = sm[0];
}

// single small block: exclusive scan over the 391 block sums
__global__ void k_blkscan() {
    __shared__ int sm[512];
    int tid = threadIdx.x;
    sm[tid] = (tid < NB) ? g_blk[tid] : 0;
    __syncthreads();
    for (int d = 1; d < 512; d <<= 1) {
        int t = (tid >= d) ? sm[tid - d] : 0;
        __syncthreads();
        sm[tid] += t;
        __syncthreads();
    }
    if (tid < NB) g_blk[tid] = sm[tid] - ((tid < NB) ? 0 : 0) - ((tid < NB) ? (tid < NB ? ((tid < NB) ? 0 : 0) : 0) : 0), g_blk[tid] = sm[tid];
    // store inclusive; consumer subtracts own count range via local exclusive scan base
    if (tid == 0 && NB < 512) { /* nothing */ }
}

// per-block: local exclusive scan of 256 counts, add block prefix, emit offsets,
// self-loop, and cursor. Uses inclusive g_blk => block base = g_blk[b] - blocksum.
__global__ void k_offsets() {
    __shared__ int sm[SCAN_BLK];
    int b = blockIdx.x;
    int n = b * SCAN_BLK + threadIdx.x;
    int c = (n < NN) ? g_cnt[n] : 0;
    sm[threadIdx.x] = c;
    __syncthreads();
    // Hillis-Steele inclusive scan over 256
    for (int d = 1; d < SCAN_BLK; d <<= 1) {
        int t = (threadIdx.x >= d) ? sm[threadIdx.x - d] : 0;
        __syncthreads();
        sm[threadIdx.x] += t;
        __syncthreads();
    }
    int blocksum = sm[SCAN_BLK - 1];
    int base = g_blk[b] - blocksum;               // exclusive block prefix
    int run = base + sm[threadIdx.x] - c;         // exclusive node prefix
    if (n < NN) {
        g_off[n] = run;
        g_csr[run] = n;          // self-loop first
        g_cnt[n] = run + 1;      // scatter cursor after self-loop
        if (n == NN - 1) g_off[NN] = run + c;
    }
}

__global__ void k_scatter(const int4* __restrict__ src4, const int4* __restrict__ dst4) {
    int e = blockIdx.x * blockDim.x + threadIdx.x;
    if (e >= NE / 4) return;
    int4 s = src4[e];
    int4 d = dst4[e];
    g_csr[atomicAdd(&g_cnt[d.x], 1)] = s.x;
    g_csr[atomicAdd(&g_cnt[d.y], 1)] = s.y;
    g_csr[atomicAdd(&g_cnt[d.z], 1)] = s.z;
    g_csr[atomicAdd(&g_cnt[d.w], 1)] = s.w;
}

// ---------------- layer 1 node transform ----------------
__global__ void k_node1(const float* __restrict__ x, const float* __restrict__ W,
                        const float* __restrict__ as_, const float* __restrict__ ad_) {
    int n = blockIdx.x * blockDim.x + threadIdx.x;
    if (n >= NN) return;
    float x0 = x[n * 3 + 0], x1 = x[n * 3 + 1], x2 = x[n * 3 + 2];
    float als0 = 0.f, als1 = 0.f, ald0 = 0.f, ald1 = 0.f;
#pragma unroll
    for (int c = 0; c < 32; c++) {
        float h = fmaf(x0, __ldg(&W[c]), fmaf(x1, __ldg(&W[32 + c]), x2 * __ldg(&W[64 + c])));
        g_h[n * 32 + c] = h;
        float vs = h * __ldg(&as_[c]), vd = h * __ldg(&ad_[c]);
        if (c < 16) { als0 += vs; ald0 += vd; }
        else        { als1 += vs; ald1 += vd; }
    }
    g_als[n * 2 + 0] = als0; g_als[n * 2 + 1] = als1;
    g_ald[n * 2 + 0] = ald0; g_ald[n * 2 + 1] = ald1;
}

__device__ __forceinline__ float lrelu(float v) { return v > 0.f ? v : 0.2f * v; }

// ---------------- edge aggregation, H=2 CH=32: one warp per dst ----------------
__global__ void __launch_bounds__(256) k_edge2() {
    __shared__ int   s_s[NW][SMAX];
    __shared__ float s_a[NW][SMAX * 2];   // [jj][h] interleaved (float2 per edge)
    int widx = threadIdx.x >> 5;
    int lane = threadIdx.x & 31;
    int w = blockIdx.x * NW + widx;       // NN % NW == 0 -> always valid

    int start = g_off[w];
    int deg   = g_off[w + 1] - start;
    float2 aldv = ((const float2*)g_ald)[w];

    // phase A: exp(logit) per edge, denominator, cache (src, e0, e1)
    float ss0 = 0.f, ss1 = 0.f;
    for (int jj = lane; jj < deg; jj += 32) {
        int s = g_csr[start + jj];
        float2 av = ((const float2*)g_als)[s];
        float e0 = __expf(lrelu(av.x + aldv.x));
        float e1 = __expf(lrelu(av.y + aldv.y));
        ss0 += e0; ss1 += e1;
        if (jj < SMAX) {
            s_s[widx][jj] = s;
            ((float2*)s_a[widx])[jj] = make_float2(e0, e1);
        }
    }
#pragma unroll
    for (int o = 16; o > 0; o >>= 1) {
        ss0 += __shfl_xor_sync(0xffffffffu, ss0, o);
        ss1 += __shfl_xor_sync(0xffffffffu, ss1, o);
    }
    __syncwarp();
    int   hsel  = lane >> 4;
    float inv_l = 1.f / ((hsel ? ss1 : ss0) + 1e-16f);
    float aldh  = hsel ? aldv.y : aldv.x;

    // phase C: lane = channel; 8-wide unrolled gather for deep MLP
    float acc = 0.f;
    int lim = min(deg, SMAX);
    int jj = 0;
    for (; jj + 8 <= lim; jj += 8) {
        int sreg[8]; float areg[8];
#pragma unroll
        for (int u = 0; u < 8; u++) {
            sreg[u] = s_s[widx][jj + u];
            areg[u] = s_a[widx][(jj + u) * 2 + hsel];
        }
        float vreg[8];
#pragma unroll
        for (int u = 0; u < 8; u++) vreg[u] = g_h[sreg[u] * 32 + lane];
#pragma unroll
        for (int u = 0; u < 8; u++) acc = fmaf(areg[u], vreg[u], acc);
    }
#pragma unroll 1
    for (; jj < lim; jj++)
        acc = fmaf(s_a[widx][jj * 2 + hsel], g_h[s_s[widx][jj] * 32 + lane], acc);
#pragma unroll 1
    for (; jj < deg; jj++) {          // overflow fallback (deg > SMAX; ~never)
        int s = g_csr[start + jj];
        float2 av = ((const float2*)g_als)[s];
        float v = (hsel ? av.y : av.x) + aldh;
        acc = fmaf(__expf(lrelu(v)), g_h[s * 32 + lane], acc);
    }
    g_o[w * 32 + lane] = acc * inv_l;
}

// ---------------- layer 3 edges (H=1, CH=8) fused with output head ----------------
__global__ void __launch_bounds__(256) k_edge1_final(
        const float* __restrict__ b3, const float* __restrict__ Wo,
        const float* __restrict__ bo, float* __restrict__ out) {
    __shared__ int   s_s[NW][SMAX];
    __shared__ float s_a[NW][SMAX];
    int widx = threadIdx.x >> 5;
    int lane = threadIdx.x & 31;
    int w = blockIdx.x * NW + widx;

    int start = g_off[w];
    int deg   = g_off[w + 1] - start;
    float aldv = g_ald[w];

    float ss = 0.f;
    for (int jj = lane; jj < deg; jj += 32) {
        int s = g_csr[start + jj];
        float e = __expf(lrelu(g_als[s] + aldv));
        ss += e;
        if (jj < SMAX) { s_s[widx][jj] = s; s_a[widx][jj] = e; }
    }
#pragma unroll
    for (int o = 16; o > 0; o >>= 1) ss += __shfl_xor_sync(0xffffffffu, ss, o);
    __syncwarp();
    float inv = 1.f / (ss + 1e-16f);

    // phase C: lane = (edge group, channel): 4 edges x 8 channels
    int grp = lane >> 3, c = lane & 7;
    float acc = 0.f;
    int lim = min(deg, SMAX);
    for (int jj = grp; jj < lim; jj += 4)
        acc = fmaf(s_a[widx][jj], g_h[s_s[widx][jj] * 8 + c], acc);
#pragma unroll 1
    for (int jj = lim + grp; jj < deg; jj += 4) {   // overflow fallback
        int s = g_csr[start + jj];
        acc = fmaf(__expf(lrelu(g_als[s] + aldv)), g_h[s * 8 + c], acc);
    }
    acc += __shfl_xor_sync(0xffffffffu, acc, 8);
    acc += __shfl_xor_sync(0xffffffffu, acc, 16);

    // fused head: y = elu(out3 + b3) @ Wo + bo
    float z = acc * inv + __ldg(&b3[c]);
    z = z > 0.f ? z : expm1f(z);
    float p = z * __ldg(&Wo[c]);
    p += __shfl_xor_sync(0xffffffffu, p, 1);
    p += __shfl_xor_sync(0xffffffffu, p, 2);
    p += __shfl_xor_sync(0xffffffffu, p, 4);
    if (lane == 0) out[w] = p + __ldg(&bo[0]);
}

// ---------------- mid node transform ----------------
template <int CIN, int COUT, int H>
__global__ void k_mid(const float* __restrict__ b, const float* __restrict__ W,
                      const float* __restrict__ as_, const float* __restrict__ ad_) {
    __shared__ float sW[CIN * COUT];
    __shared__ float sb[CIN];
    __shared__ float sas[COUT], sad[COUT];
    for (int i = threadIdx.x; i < CIN * COUT; i += blockDim.x) sW[i] = W[i];
    for (int i = threadIdx.x; i < CIN; i += blockDim.x) sb[i] = b[i];
    for (int i = threadIdx.x; i < COUT; i += blockDim.x) { sas[i] = as_[i]; sad[i] = ad_[i]; }
    __syncthreads();

    int n = blockIdx.x * blockDim.x + threadIdx.x;
    if (n >= NN) return;
    float z[CIN];
#pragma unroll
    for (int i = 0; i < CIN; i++) {
        float v = g_o[n * CIN + i] + sb[i];
        z[i] = v > 0.f ? v : expm1f(v);              // elu
    }
    const int C = COUT / H;
    float als[H], ald[H];
#pragma unroll
    for (int h = 0; h < H; h++) { als[h] = 0.f; ald[h] = 0.f; }
#pragma unroll
    for (int c = 0; c < COUT; c++) {
        float hv = 0.f;
#pragma unroll
        for (int i = 0; i < CIN; i++) hv = fmaf(z[i], sW[i * COUT + c], hv);
        g_h[n * COUT + c] = hv;
        int h = c / C;
        als[h] = fmaf(hv, sas[c], als[h]);
        ald[h] = fmaf(hv, sad[c], ald[h]);
    }
#pragma unroll
    for (int h = 0; h < H; h++) { g_als[n * H + h] = als[h]; g_ald[n * H + h] = ald[h]; }
}

// ---------------- launch ----------------
extern "C" void kernel_launch(void* const* d_in, const int* in_sizes, int n_in,
                              void* d_out, int out_size) {
    const float* x   = (const float*)d_in[0];
    const int*   ei  = (const int*)d_in[1];
    const float* W1  = (const float*)d_in[2];
    const float* as1 = (const float*)d_in[3];
    const float* ad1 = (const float*)d_in[4];
    const float* b1  = (const float*)d_in[5];
    const float* W2  = (const float*)d_in[6];
    const float* as2 = (const float*)d_in[7];
    const float* ad2 = (const float*)d_in[8];
    const float* b2  = (const float*)d_in[9];
    const float* W3  = (const float*)d_in[10];
    const float* as3 = (const float*)d_in[11];
    const float* ad3 = (const float*)d_in[12];
    const float* b3  = (const float*)d_in[13];
    const float* Wo  = (const float*)d_in[14];
    const float* bo  = (const float*)d_in[15];
    float* out = (float*)d_out;

    const int4* src4 = (const int4*)ei;            // edge_index[0]
    const int4* dst4 = (const int4*)(ei + NE);     // edge_index[1]

    // CSR build by dst (parallel 3-level scan; self-loops folded in)
    k_zero<<<(NN + 255) / 256, 256>>>();
    k_count<<<(NE / 4 + 255) / 256, 256>>>(dst4);
    k_blksum<<<NB, SCAN_BLK>>>();
    k_blkscan<<<1, 512>>>();
    k_offsets<<<NB, SCAN_BLK>>>();
    k_scatter<<<(NE / 4 + 255) / 256, 256>>>(src4, dst4);

    const int EB = NN / NW;   // 12500 blocks, one warp per dst node
    // layer 1 (H=2, C=16)
    k_node1<<<(NN + 255) / 256, 256>>>(x, W1, as1, ad1);
    k_edge2<<<EB, 256>>>();
    // layer 2 (H=2, C=16)
    k_mid<32, 32, 2><<<(NN + 255) / 256, 256>>>(b1, W2, as2, ad2);
    k_edge2<<<EB, 256>>>();
    // layer 3 (H=1, C=8) + fused output head
    k_mid<32, 8, 1><<<(NN + 255) / 256, 256>>>(b2, W3, as3, ad3);
    k_edge1_final<<<EB, 256>>>(b3, Wo, bo, out);

    (void)in_sizes; (void)n_in; (void)out_size;
}